// round 13
// baseline (speedup 1.0000x reference)
#include <cuda_runtime.h>
#include <cuda_bf16.h>
#include <cstdint>

// ============================================================================
// Problem constants
// ============================================================================
static constexpr int NROW = 6144;
static constexpr int DIM  = 768;
static constexpr int DIM_U4 = DIM / 8;   // 96 uint4 per row (bf16)
static constexpr float INV_T_LOG2E = 20.609929155566063f;  // (1/0.07)*log2(e)

// GEMM tiling: CTA 128x128, 8 warps (2x4), warp tile 64x32, K staged at 64
static constexpr int BK      = 64;
static constexpr int NSTAGES = DIM / BK;   // 12
static constexpr int GRID    = NROW / 128; // 48

// Dynamic SMEM: A0@0(16K) B0@16K A1@32K B1@48K, rowacc@64K, colacc@64K+512
static constexpr int SMEM_ACC   = 65536;
static constexpr int SMEM_TOTAL = 65536 + 1024;

// ============================================================================
// Device scratch (no runtime allocation allowed)
// ============================================================================
__device__ uint4 g_fbf16[NROW * DIM_U4];   // normalized feats, bf16 row-major
__device__ float g_norms[NROW];
__device__ float g_rowsum[NROW];           // sum_{j!=i} exp(sim_ij)
__device__ float g_num[NROW];              // logsumexp over positives

// ============================================================================
// PTX helpers (base ISA only — compiles for .target sm_103)
// ============================================================================
__device__ __forceinline__ uint32_t smem_u32(const void* p) {
    uint32_t a;
    asm("{ .reg .u64 t; cvta.to.shared.u64 t, %1; cvt.u32.u64 %0, t; }"
        : "=r"(a) : "l"(p));
    return a;
}

__device__ __forceinline__ void ldsm_x4(uint32_t r[4], uint32_t addr) {
    asm volatile("ldmatrix.sync.aligned.m8n8.x4.shared.b16 {%0,%1,%2,%3}, [%4];"
                 : "=r"(r[0]), "=r"(r[1]), "=r"(r[2]), "=r"(r[3]) : "r"(addr));
}

__device__ __forceinline__ void mma16816(float c[4], const uint32_t a[4],
                                         const uint32_t b[2]) {
    asm volatile(
        "mma.sync.aligned.m16n8k16.row.col.f32.bf16.bf16.f32 "
        "{%0,%1,%2,%3}, {%4,%5,%6,%7}, {%8,%9}, {%0,%1,%2,%3};"
        : "+f"(c[0]), "+f"(c[1]), "+f"(c[2]), "+f"(c[3])
        : "r"(a[0]), "r"(a[1]), "r"(a[2]), "r"(a[3]), "r"(b[0]), "r"(b[1]));
}

#define CP_ASYNC16(dst, src) \
    asm volatile("cp.async.cg.shared.global [%0], [%1], 16;" \
                 :: "r"(dst), "l"(src) : "memory")
#define CP_ASYNC_COMMIT() \
    asm volatile("cp.async.commit_group;" ::: "memory")
#define CP_ASYNC_WAIT(n) \
    asm volatile("cp.async.wait_group %0;" :: "n"(n) : "memory")

// SW128-style swizzle on byte offsets within a 128B-row tile
__device__ __forceinline__ uint32_t swz(uint32_t off) {
    return off ^ ((off >> 3) & 0x70);
}

// exp(d/0.07) via FFMA-only exp2 (no MUFU). |d| <= ~1 -> |y| <= ~21.
// Degree-5 poly on f in [-0.5, 0.5]: rel err ~2.4e-6.
__device__ __forceinline__ float fast_exp_scaled(float d) {
    float y = d * INV_T_LOG2E;
    int   ei = __float2int_rn(y);
    float f  = y - (float)ei;
    float p = 0.0013333558f;
    p = fmaf(p, f, 0.0096181291f);
    p = fmaf(p, f, 0.0555041087f);
    p = fmaf(p, f, 0.2402265070f);
    p = fmaf(p, f, 0.6931471806f);
    p = fmaf(p, f, 1.0f);
    return p * __int_as_float((ei + 127) << 23);
}

// ============================================================================
// Kernel 1: L2-normalize rows -> bf16; stash norms; zero rowsum
// ============================================================================
__global__ void normalize_kernel(const float* __restrict__ feats) {
    int row = blockIdx.x;
    int t   = threadIdx.x;  // 256 threads
    const float* src = feats + (size_t)row * DIM;
    float v0 = src[t], v1 = src[t + 256], v2 = src[t + 512];
    float ss = v0 * v0 + v1 * v1 + v2 * v2;
    #pragma unroll
    for (int o = 16; o; o >>= 1) ss += __shfl_xor_sync(0xFFFFFFFFu, ss, o);
    __shared__ float sred[8];
    __shared__ float s_rn;
    if ((t & 31) == 0) sred[t >> 5] = ss;
    __syncthreads();
    if (t == 0) {
        float tot = 0.f;
        #pragma unroll
        for (int i = 0; i < 8; ++i) tot += sred[i];
        float nrm = fmaxf(sqrtf(tot), 1e-12f);
        g_norms[row]  = nrm;
        g_rowsum[row] = 0.f;
        s_rn = 1.f / nrm;
    }
    __syncthreads();
    float rn = s_rn;
    __nv_bfloat16* dst = ((__nv_bfloat16*)g_fbf16) + (size_t)row * DIM;
    dst[t]       = __float2bfloat16(v0 * rn);
    dst[t + 256] = __float2bfloat16(v1 * rn);
    dst[t + 512] = __float2bfloat16(v2 * rn);
}

// ============================================================================
// Kernel 2: numerator — exact fp32 positives (groups of 3 rows)
// ============================================================================
__global__ void numerator_kernel(const float* __restrict__ feats) {
    int g = blockIdx.x * (blockDim.x >> 5) + (threadIdx.x >> 5);
    int lane = threadIdx.x & 31;
    if (g >= NROW / 3) return;
    const float* a = feats + (size_t)(3 * g + 0) * DIM;
    const float* b = feats + (size_t)(3 * g + 1) * DIM;
    const float* c = feats + (size_t)(3 * g + 2) * DIM;
    float dab = 0.f, dac = 0.f, dbc = 0.f;
    for (int k = lane; k < DIM; k += 32) {
        float va = a[k], vb = b[k], vc = c[k];
        dab = fmaf(va, vb, dab);
        dac = fmaf(va, vc, dac);
        dbc = fmaf(vb, vc, dbc);
    }
    #pragma unroll
    for (int o = 16; o; o >>= 1) {
        dab += __shfl_xor_sync(0xFFFFFFFFu, dab, o);
        dac += __shfl_xor_sync(0xFFFFFFFFu, dac, o);
        dbc += __shfl_xor_sync(0xFFFFFFFFu, dbc, o);
    }
    if (lane == 0) {
        float na = g_norms[3 * g], nb = g_norms[3 * g + 1], nc = g_norms[3 * g + 2];
        const float invT = 1.0f / 0.07f;
        float sab = dab / (na * nb) * invT;
        float sac = dac / (na * nc) * invT;
        float sbc = dbc / (nb * nc) * invT;
        g_num[3 * g + 0] = logf(expf(sab) + expf(sac));
        g_num[3 * g + 1] = logf(expf(sab) + expf(sbc));
        g_num[3 * g + 2] = logf(expf(sac) + expf(sbc));
    }
}

// ============================================================================
// Kernel 3: 128x128 bf16 GEMM tile (mma.sync) + fused exp/diag-mask/row+col sums.
// Upper-triangular tiles only; symmetry supplies the mirror tile via col sums.
// ============================================================================
__global__ __launch_bounds__(256, 2) void gemm_lse_kernel() {
    const int bm = blockIdx.y, bn = blockIdx.x;
    if (bn < bm) return;   // symmetric: skip lower triangle

    extern __shared__ __align__(1024) char smem[];
    const uint32_t sb = smem_u32(smem);
    const int tid  = threadIdx.x;
    const int lane = tid & 31;
    const int w    = tid >> 5;            // 8 warps
    const int wm   = (w >> 2) * 64;       // warp row offset within tile
    const int wn   = (w & 3) * 32;        // warp col offset within tile
    const int m0 = bm * 128, n0 = bn * 128;
    const bool diag = (bm == bn);

    float* rowacc = (float*)(smem + SMEM_ACC);
    float* colacc = rowacc + 128;
    if (tid < 128) { rowacc[tid] = 0.f; colacc[tid] = 0.f; }

    const uint4* __restrict__ gA = g_fbf16 + (size_t)m0 * DIM_U4;
    const uint4* __restrict__ gB = g_fbf16 + (size_t)n0 * DIM_U4;

    float acc[4][4][4];
    #pragma unroll
    for (int i = 0; i < 4; ++i)
        #pragma unroll
        for (int j = 0; j < 4; ++j)
            #pragma unroll
            for (int k = 0; k < 4; ++k) acc[i][j][k] = 0.f;

    // ---- stage loader: 16B cp.async per thread x 4 iters per operand ----
    auto load_stage = [&](int c, int s) {
        uint32_t aBase = sb + s * 32768;
        uint32_t bBase = aBase + 16384;
        #pragma unroll
        for (int i = 0; i < 4; ++i) {
            int idx = tid + i * 256;       // 1024 chunks: 128 rows x 8
            int r = idx >> 3, ch = idx & 7;
            uint32_t off = swz((uint32_t)(r * 128 + ch * 16));
            CP_ASYNC16(aBase + off, &gA[r * DIM_U4 + c * 8 + ch]);
            CP_ASYNC16(bBase + off, &gB[r * DIM_U4 + c * 8 + ch]);
        }
        CP_ASYNC_COMMIT();
    };

    // ---- compute one K=64 stage: 4 k16-steps x (4x4) mma per warp ----
    const int arow  = wm + (lane & 15);
    const uint32_t acolp = (uint32_t)((lane >> 4) << 4);
    const int brow  = wn + ((lane >> 4) << 3) + (lane & 7);
    const uint32_t bcolp = (uint32_t)(((lane >> 3) & 1) << 4);

    auto compute_stage = [&](int s) {
        uint32_t aBase = sb + s * 32768;
        uint32_t bBase = aBase + 16384;
        #pragma unroll
        for (int ks = 0; ks < 4; ++ks) {
            uint32_t af[4][4];
            #pragma unroll
            for (int mt = 0; mt < 4; ++mt) {
                uint32_t off = swz((uint32_t)((arow + mt * 16) * 128) +
                                   (uint32_t)(ks * 32) + acolp);
                ldsm_x4(af[mt], aBase + off);
            }
            uint32_t bf[4][2];
            #pragma unroll
            for (int p = 0; p < 2; ++p) {
                uint32_t t4[4];
                uint32_t off = swz((uint32_t)((brow + p * 16) * 128) +
                                   (uint32_t)(ks * 32) + bcolp);
                ldsm_x4(t4, bBase + off);
                bf[2 * p][0]     = t4[0]; bf[2 * p][1]     = t4[1];
                bf[2 * p + 1][0] = t4[2]; bf[2 * p + 1][1] = t4[3];
            }
            #pragma unroll
            for (int mt = 0; mt < 4; ++mt)
                #pragma unroll
                for (int nt = 0; nt < 4; ++nt)
                    mma16816(acc[mt][nt], af[mt], bf[nt]);
        }
    };

    // ---- 2-deep software pipeline over 12 K-stages ----
    load_stage(0, 0);
    #pragma unroll 1
    for (int c = 0; c < NSTAGES; ++c) {
        if (c + 1 < NSTAGES) {
            load_stage(c + 1, (c + 1) & 1);
            CP_ASYNC_WAIT(1);
        } else {
            CP_ASYNC_WAIT(0);
        }
        __syncthreads();
        compute_stage(c & 1);
        __syncthreads();
    }

    // ---- epilogue: exp + diag mask; per-row and per-col partials ----
    float rowp[4][2], colp[4][2];
    #pragma unroll
    for (int i = 0; i < 4; ++i) {
        rowp[i][0] = rowp[i][1] = 0.f;
        colp[i][0] = colp[i][1] = 0.f;
    }
    const int rl0 = wm + (lane >> 2);
    const int cl0 = wn + 2 * (lane & 3);
    #pragma unroll
    for (int mt = 0; mt < 4; ++mt) {
        int r0 = rl0 + mt * 16, r1 = r0 + 8;
        #pragma unroll
        for (int nt = 0; nt < 4; ++nt) {
            int c0 = cl0 + nt * 8, c1 = c0 + 1;
            float e00 = fast_exp_scaled(acc[mt][nt][0]);
            float e01 = fast_exp_scaled(acc[mt][nt][1]);
            float e10 = fast_exp_scaled(acc[mt][nt][2]);
            float e11 = fast_exp_scaled(acc[mt][nt][3]);
            if (diag) {
                if (r0 == c0) e00 = 0.f;
                if (r0 == c1) e01 = 0.f;
                if (r1 == c0) e10 = 0.f;
                if (r1 == c1) e11 = 0.f;
            }
            rowp[mt][0] += e00 + e01;
            rowp[mt][1] += e10 + e11;
            colp[nt][0] += e00 + e10;
            colp[nt][1] += e01 + e11;
        }
    }
    // row reduce: lanes sharing (lane>>2) hold same rows
    #pragma unroll
    for (int mt = 0; mt < 4; ++mt)
        #pragma unroll
        for (int h = 0; h < 2; ++h) {
            float v = rowp[mt][h];
            v += __shfl_xor_sync(0xFFFFFFFFu, v, 1);
            v += __shfl_xor_sync(0xFFFFFFFFu, v, 2);
            if ((lane & 3) == 0)
                atomicAdd(&rowacc[wm + mt * 16 + (lane >> 2) + 8 * h], v);
        }
    // col reduce: lanes sharing (lane&3) hold same cols
    #pragma unroll
    for (int nt = 0; nt < 4; ++nt)
        #pragma unroll
        for (int j = 0; j < 2; ++j) {
            float v = colp[nt][j];
            v += __shfl_xor_sync(0xFFFFFFFFu, v, 4);
            v += __shfl_xor_sync(0xFFFFFFFFu, v, 8);
            v += __shfl_xor_sync(0xFFFFFFFFu, v, 16);
            if (lane < 4)
                atomicAdd(&colacc[wn + nt * 8 + 2 * lane + j], v);
        }
    __syncthreads();
    if (tid < 128) {
        atomicAdd(&g_rowsum[m0 + tid], rowacc[tid]);
        if (!diag) atomicAdd(&g_rowsum[n0 + tid], colacc[tid]);
    }
}

// ============================================================================
// Kernel 4: final reduction -> loss scalar
// ============================================================================
__global__ void finalize_kernel(float* __restrict__ out) {
    int t = threadIdx.x;  // 1024
    float acc = 0.f;
    for (int i = t; i < NROW; i += 1024)
        acc += logf(g_rowsum[i]) - g_num[i];
    #pragma unroll
    for (int o = 16; o; o >>= 1) acc += __shfl_xor_sync(0xFFFFFFFFu, acc, o);
    __shared__ float sr[32];
    if ((t & 31) == 0) sr[t >> 5] = acc;
    __syncthreads();
    if (t < 32) {
        float v = sr[t];
        #pragma unroll
        for (int o = 16; o; o >>= 1) v += __shfl_xor_sync(0xFFFFFFFFu, v, o);
        if (t == 0) out[0] = v * (1.0f / (float)NROW);
    }
}

// ============================================================================
// Launch
// ============================================================================
extern "C" void kernel_launch(void* const* d_in, const int* in_sizes, int n_in,
                              void* d_out, int out_size) {
    const float* feats = (const float*)d_in[0];
    float* out = (float*)d_out;
    (void)in_sizes; (void)n_in; (void)out_size;

    normalize_kernel<<<NROW, 256>>>(feats);
    numerator_kernel<<<(NROW / 3 + 7) / 8, 256>>>(feats);

    cudaFuncSetAttribute(gemm_lse_kernel,
                         cudaFuncAttributeMaxDynamicSharedMemorySize, SMEM_TOTAL);
    dim3 grid(GRID, GRID);
    gemm_lse_kernel<<<grid, 256, SMEM_TOTAL>>>();

    finalize_kernel<<<1, 1024>>>(out);
}

// round 14
// speedup vs baseline: 1.1347x; 1.1347x over previous
#include <cuda_runtime.h>
#include <cuda_bf16.h>
#include <cstdint>

// ============================================================================
// Problem constants
// ============================================================================
static constexpr int NROW = 6144;
static constexpr int DIM  = 768;
static constexpr int DIM_U4 = DIM / 8;   // 96 uint4 per row (bf16)
static constexpr float INV_T = 14.285714285714286f;   // 1/0.07

// GEMM tiling: CTA 128x128, 8 warps (2x4), warp tile 64x32, K staged at 64
static constexpr int NSTAGES = DIM / 64;    // 12
static constexpr int GRID    = NROW / 128;  // 48
static constexpr int NTILES  = GRID * (GRID + 1) / 2;  // 1176 upper-tri tiles

// Dynamic SMEM: 3 stages x 32KB (A 16K + B 16K), then acc arrays
static constexpr int STAGE_BYTES = 32768;
static constexpr int SMEM_ACC    = 3 * STAGE_BYTES;     // 98304
static constexpr int SMEM_TOTAL  = SMEM_ACC + 1536;     // row/col/pos acc

// ============================================================================
// Device scratch (no runtime allocation allowed)
// ============================================================================
__device__ uint4 g_fbf16[NROW * DIM_U4];   // normalized feats, bf16 row-major
__device__ float g_rowsum[NROW];           // sum_{j!=i} exp(sim_ij)
__device__ float g_possum[NROW];           // sum over positives exp(sim_ij)

// ============================================================================
// PTX helpers (base ISA only — compiles for .target sm_103)
// ============================================================================
__device__ __forceinline__ uint32_t smem_u32(const void* p) {
    uint32_t a;
    asm("{ .reg .u64 t; cvta.to.shared.u64 t, %1; cvt.u32.u64 %0, t; }"
        : "=r"(a) : "l"(p));
    return a;
}

__device__ __forceinline__ void ldsm_x4(uint32_t r[4], uint32_t addr) {
    asm volatile("ldmatrix.sync.aligned.m8n8.x4.shared.b16 {%0,%1,%2,%3}, [%4];"
                 : "=r"(r[0]), "=r"(r[1]), "=r"(r[2]), "=r"(r[3]) : "r"(addr));
}

__device__ __forceinline__ void mma16816(float c[4], const uint32_t a[4],
                                         const uint32_t b[2]) {
    asm volatile(
        "mma.sync.aligned.m16n8k16.row.col.f32.bf16.bf16.f32 "
        "{%0,%1,%2,%3}, {%4,%5,%6,%7}, {%8,%9}, {%0,%1,%2,%3};"
        : "+f"(c[0]), "+f"(c[1]), "+f"(c[2]), "+f"(c[3])
        : "r"(a[0]), "r"(a[1]), "r"(a[2]), "r"(a[3]), "r"(b[0]), "r"(b[1]));
}

#define CP_ASYNC16(dst, src) \
    asm volatile("cp.async.cg.shared.global [%0], [%1], 16;" \
                 :: "r"(dst), "l"(src) : "memory")
#define CP_ASYNC_COMMIT() \
    asm volatile("cp.async.commit_group;" ::: "memory")
#define CP_ASYNC_WAIT(n) \
    asm volatile("cp.async.wait_group %0;" :: "n"(n) : "memory")

// SW128-style swizzle on byte offsets within a 128B-row tile
__device__ __forceinline__ uint32_t swz(uint32_t off) {
    return off ^ ((off >> 3) & 0x70);
}

// exp(d / 0.07): 1 FMUL + 1 MUFU (hardware exp2), rel err ~1e-6
__device__ __forceinline__ float fast_exp_scaled(float d) {
    return __expf(d * INV_T);
}

// ============================================================================
// Kernel 1: L2-normalize rows -> bf16; zero accumulators and output
// ============================================================================
__global__ void normalize_kernel(const float* __restrict__ feats,
                                 float* __restrict__ out) {
    int row = blockIdx.x;
    int t   = threadIdx.x;  // 256 threads
    const float* src = feats + (size_t)row * DIM;
    float v0 = src[t], v1 = src[t + 256], v2 = src[t + 512];
    float ss = v0 * v0 + v1 * v1 + v2 * v2;
    #pragma unroll
    for (int o = 16; o; o >>= 1) ss += __shfl_xor_sync(0xFFFFFFFFu, ss, o);
    __shared__ float sred[8];
    __shared__ float s_rn;
    if ((t & 31) == 0) sred[t >> 5] = ss;
    __syncthreads();
    if (t == 0) {
        float tot = 0.f;
        #pragma unroll
        for (int i = 0; i < 8; ++i) tot += sred[i];
        float nrm = fmaxf(sqrtf(tot), 1e-12f);
        g_rowsum[row] = 0.f;
        g_possum[row] = 0.f;
        if (row == 0) out[0] = 0.f;
        s_rn = 1.f / nrm;
    }
    __syncthreads();
    float rn = s_rn;
    __nv_bfloat16* dst = ((__nv_bfloat16*)g_fbf16) + (size_t)row * DIM;
    dst[t]       = __float2bfloat16(v0 * rn);
    dst[t + 256] = __float2bfloat16(v1 * rn);
    dst[t + 512] = __float2bfloat16(v2 * rn);
}

// ============================================================================
// Kernel 2: 128x128 bf16 GEMM tile (mma.sync) + fused exp / diag mask /
// row+col sums / positive-pair sums. Upper-triangular tiles only; the
// symmetric mirror is supplied via column sums.
// ============================================================================
__global__ __launch_bounds__(256, 2) void gemm_lse_kernel() {
    // 1D -> upper-triangular (bm, bn) mapping
    int idx = blockIdx.x, bm = 0, rem = GRID;
    while (idx >= rem) { idx -= rem; --rem; ++bm; }
    const int bn = bm + idx;

    extern __shared__ __align__(1024) char smem[];
    const uint32_t sb = smem_u32(smem);
    const int tid  = threadIdx.x;
    const int lane = tid & 31;
    const int w    = tid >> 5;            // 8 warps
    const int wm   = (w >> 2) * 64;       // warp row offset within tile
    const int wn   = (w & 3) * 32;        // warp col offset within tile
    const int m0 = bm * 128, n0 = bn * 128;
    const bool diag = (bm == bn);
    const bool adj  = (bn == bm + 1);     // may hold straddling positive pairs

    float* rowacc = (float*)(smem + SMEM_ACC);
    float* colacc = rowacc + 128;
    float* posacc = colacc + 128;
    if (tid < 128) { rowacc[tid] = 0.f; colacc[tid] = 0.f; posacc[tid] = 0.f; }

    const uint4* __restrict__ gA = g_fbf16 + (size_t)m0 * DIM_U4;
    const uint4* __restrict__ gB = g_fbf16 + (size_t)n0 * DIM_U4;

    float acc[4][4][4];
    #pragma unroll
    for (int i = 0; i < 4; ++i)
        #pragma unroll
        for (int j = 0; j < 4; ++j)
            #pragma unroll
            for (int k = 0; k < 4; ++k) acc[i][j][k] = 0.f;

    // ---- stage loader: 16B cp.async per thread x 4 iters per operand ----
    auto load_stage = [&](int c, int s) {
        uint32_t aBase = sb + s * STAGE_BYTES;
        uint32_t bBase = aBase + 16384;
        #pragma unroll
        for (int i = 0; i < 4; ++i) {
            int id = tid + i * 256;       // 1024 chunks: 128 rows x 8
            int r = id >> 3, ch = id & 7;
            uint32_t off = swz((uint32_t)(r * 128 + ch * 16));
            CP_ASYNC16(aBase + off, &gA[r * DIM_U4 + c * 8 + ch]);
            CP_ASYNC16(bBase + off, &gB[r * DIM_U4 + c * 8 + ch]);
        }
        CP_ASYNC_COMMIT();
    };

    // ---- compute one K=64 stage: 4 k16-steps x (4x4) mma per warp ----
    const int arow  = wm + (lane & 15);
    const uint32_t acolp = (uint32_t)((lane >> 4) << 4);
    const int brow  = wn + ((lane >> 4) << 3) + (lane & 7);
    const uint32_t bcolp = (uint32_t)(((lane >> 3) & 1) << 4);

    auto compute_stage = [&](int s) {
        uint32_t aBase = sb + s * STAGE_BYTES;
        uint32_t bBase = aBase + 16384;
        #pragma unroll
        for (int ks = 0; ks < 4; ++ks) {
            uint32_t af[4][4];
            #pragma unroll
            for (int mt = 0; mt < 4; ++mt) {
                uint32_t off = swz((uint32_t)((arow + mt * 16) * 128) +
                                   (uint32_t)(ks * 32) + acolp);
                ldsm_x4(af[mt], aBase + off);
            }
            uint32_t bf[4][2];
            #pragma unroll
            for (int p = 0; p < 2; ++p) {
                uint32_t t4[4];
                uint32_t off = swz((uint32_t)((brow + p * 16) * 128) +
                                   (uint32_t)(ks * 32) + bcolp);
                ldsm_x4(t4, bBase + off);
                bf[2 * p][0]     = t4[0]; bf[2 * p][1]     = t4[1];
                bf[2 * p + 1][0] = t4[2]; bf[2 * p + 1][1] = t4[3];
            }
            #pragma unroll
            for (int mt = 0; mt < 4; ++mt)
                #pragma unroll
                for (int nt = 0; nt < 4; ++nt)
                    mma16816(acc[mt][nt], af[mt], bf[nt]);
        }
    };

    // ---- 3-stage software pipeline, one sync per K-stage ----
    load_stage(0, 0);
    load_stage(1, 1);
    #pragma unroll 1
    for (int c = 0; c < NSTAGES; ++c) {
        if (c < NSTAGES - 1) { CP_ASYNC_WAIT(1); } else { CP_ASYNC_WAIT(0); }
        __syncthreads();                   // load(c) visible; compute(c-1) done
        if (c + 2 < NSTAGES) load_stage(c + 2, (c + 2) % 3);
        compute_stage(c % 3);
    }

    // ---- epilogue: exp + diag mask; row / col / positive partials ----
    float rowp[4][2], colp[4][2], posp[4][2];
    #pragma unroll
    for (int i = 0; i < 4; ++i) {
        rowp[i][0] = rowp[i][1] = 0.f;
        colp[i][0] = colp[i][1] = 0.f;
        posp[i][0] = posp[i][1] = 0.f;
    }
    const int rl0 = wm + (lane >> 2);
    const int cl0 = wn + 2 * (lane & 3);
    #pragma unroll
    for (int mt = 0; mt < 4; ++mt) {
        int r0 = rl0 + mt * 16, r1 = r0 + 8;
        #pragma unroll
        for (int nt = 0; nt < 4; ++nt) {
            int c0 = cl0 + nt * 8, c1 = c0 + 1;
            float e00 = fast_exp_scaled(acc[mt][nt][0]);
            float e01 = fast_exp_scaled(acc[mt][nt][1]);
            float e10 = fast_exp_scaled(acc[mt][nt][2]);
            float e11 = fast_exp_scaled(acc[mt][nt][3]);
            if (diag) {
                if (r0 == c0) e00 = 0.f;
                if (r0 == c1) e01 = 0.f;
                if (r1 == c0) e10 = 0.f;
                if (r1 == c1) e11 = 0.f;
                // positives: same global group of 3 (self already zeroed)
                int gr0 = (m0 + r0) / 3, gr1 = (m0 + r1) / 3;
                int gc0 = (n0 + c0) / 3, gc1 = (n0 + c1) / 3;
                posp[mt][0] += (gr0 == gc0 ? e00 : 0.f) + (gr0 == gc1 ? e01 : 0.f);
                posp[mt][1] += (gr1 == gc0 ? e10 : 0.f) + (gr1 == gc1 ? e11 : 0.f);
            }
            if (adj && mt == 3 && nt == 0) {
                // straddling group across the 128-boundary (128 % 3 != 0):
                // only rows n0-2..n0-1 x cols n0..n0+1 can qualify (<=2 elems)
                int gr1g = m0 + r1;
                if (gr1g >= n0 - 2 && c0 <= 1) {
                    if ((gr1g / 3) == ((n0 + c0) / 3)) {
                        atomicAdd(&g_possum[gr1g], e10);
                        atomicAdd(&g_possum[n0 + c0], e10);
                    }
                    if ((gr1g / 3) == ((n0 + c1) / 3)) {
                        atomicAdd(&g_possum[gr1g], e11);
                        atomicAdd(&g_possum[n0 + c1], e11);
                    }
                }
            }
            rowp[mt][0] += e00 + e01;
            rowp[mt][1] += e10 + e11;
            colp[nt][0] += e00 + e10;
            colp[nt][1] += e01 + e11;
        }
    }
    // row reduce: lanes sharing (lane>>2) hold the same rows
    #pragma unroll
    for (int mt = 0; mt < 4; ++mt)
        #pragma unroll
        for (int h = 0; h < 2; ++h) {
            float v = rowp[mt][h];
            v += __shfl_xor_sync(0xFFFFFFFFu, v, 1);
            v += __shfl_xor_sync(0xFFFFFFFFu, v, 2);
            float q = posp[mt][h];
            q += __shfl_xor_sync(0xFFFFFFFFu, q, 1);
            q += __shfl_xor_sync(0xFFFFFFFFu, q, 2);
            if ((lane & 3) == 0) {
                int rr = wm + mt * 16 + (lane >> 2) + 8 * h;
                atomicAdd(&rowacc[rr], v);
                if (diag) atomicAdd(&posacc[rr], q);
            }
        }
    // col reduce: lanes sharing (lane&3) hold the same cols
    #pragma unroll
    for (int nt = 0; nt < 4; ++nt)
        #pragma unroll
        for (int j = 0; j < 2; ++j) {
            float v = colp[nt][j];
            v += __shfl_xor_sync(0xFFFFFFFFu, v, 4);
            v += __shfl_xor_sync(0xFFFFFFFFu, v, 8);
            v += __shfl_xor_sync(0xFFFFFFFFu, v, 16);
            if (lane < 4)
                atomicAdd(&colacc[wn + nt * 8 + 2 * lane + j], v);
        }
    __syncthreads();
    if (tid < 128) {
        atomicAdd(&g_rowsum[m0 + tid], rowacc[tid]);
        if (!diag) atomicAdd(&g_rowsum[n0 + tid], colacc[tid]);
        if (diag)  atomicAdd(&g_possum[m0 + tid], posacc[tid]);
    }
}

// ============================================================================
// Kernel 3: parallel final reduction -> loss scalar (out zeroed in normalize)
// ============================================================================
__global__ void finalize_kernel(float* __restrict__ out) {
    int i = blockIdx.x * 256 + threadIdx.x;   // 24 x 256 = 6144 threads
    float v = logf(g_rowsum[i] / g_possum[i]);
    #pragma unroll
    for (int o = 16; o; o >>= 1) v += __shfl_xor_sync(0xFFFFFFFFu, v, o);
    __shared__ float sr[8];
    int lane = threadIdx.x & 31, wrp = threadIdx.x >> 5;
    if (lane == 0) sr[wrp] = v;
    __syncthreads();
    if (threadIdx.x < 8) {
        float s = sr[threadIdx.x];
        #pragma unroll
        for (int o = 4; o; o >>= 1) s += __shfl_xor_sync(0xFFu, s, o);
        if (threadIdx.x == 0) atomicAdd(out, s * (1.0f / (float)NROW));
    }
}

// ============================================================================
// Launch
// ============================================================================
extern "C" void kernel_launch(void* const* d_in, const int* in_sizes, int n_in,
                              void* d_out, int out_size) {
    const float* feats = (const float*)d_in[0];
    float* out = (float*)d_out;
    (void)in_sizes; (void)n_in; (void)out_size;

    normalize_kernel<<<NROW, 256>>>(feats, out);

    cudaFuncSetAttribute(gemm_lse_kernel,
                         cudaFuncAttributeMaxDynamicSharedMemorySize, SMEM_TOTAL);
    gemm_lse_kernel<<<NTILES, 256, SMEM_TOTAL>>>();

    finalize_kernel<<<NROW / 256, 256>>>(out);
}

// round 15
// speedup vs baseline: 1.1670x; 1.0284x over previous
#include <cuda_runtime.h>
#include <cuda_bf16.h>
#include <cstdint>

// ============================================================================
// Problem constants
// ============================================================================
static constexpr int NROW = 6144;
static constexpr int DIM  = 768;
static constexpr int DIM_U4 = DIM / 8;   // 96 uint4 per row (bf16)
static constexpr float INV_T = 14.285714285714286f;   // 1/0.07

// GEMM tiling: CTA 128x128, 8 warps (2x4), warp tile 64x32, K staged at 64
static constexpr int NSTAGES = DIM / 64;    // 12
static constexpr int GRID    = NROW / 128;  // 48
static constexpr int NTILES  = GRID * (GRID + 1) / 2;  // 1176 upper-tri tiles

// Dynamic SMEM: 3 stages x 32KB (A 16K + B 16K), then acc arrays
static constexpr int STAGE_BYTES = 32768;
static constexpr int SMEM_ACC    = 3 * STAGE_BYTES;     // 98304
static constexpr int SMEM_TOTAL  = SMEM_ACC + 1536;     // row/col/pos acc

// ============================================================================
// Device scratch (no runtime allocation allowed)
// ============================================================================
__device__ uint4 g_fbf16[NROW * DIM_U4];   // normalized feats, bf16 row-major
__device__ float g_rowsum[NROW];           // sum_{j!=i} exp(sim_ij)
__device__ float g_possum[NROW];           // sum over positives exp(sim_ij)

// ============================================================================
// PTX helpers (base ISA only — compiles for .target sm_103)
// ============================================================================
__device__ __forceinline__ uint32_t smem_u32(const void* p) {
    uint32_t a;
    asm("{ .reg .u64 t; cvta.to.shared.u64 t, %1; cvt.u32.u64 %0, t; }"
        : "=r"(a) : "l"(p));
    return a;
}

__device__ __forceinline__ void ldsm_x4(uint32_t r[4], uint32_t addr) {
    asm volatile("ldmatrix.sync.aligned.m8n8.x4.shared.b16 {%0,%1,%2,%3}, [%4];"
                 : "=r"(r[0]), "=r"(r[1]), "=r"(r[2]), "=r"(r[3]) : "r"(addr));
}

__device__ __forceinline__ void mma16816(float c[4], const uint32_t a[4],
                                         const uint32_t b[2]) {
    asm volatile(
        "mma.sync.aligned.m16n8k16.row.col.f32.bf16.bf16.f32 "
        "{%0,%1,%2,%3}, {%4,%5,%6,%7}, {%8,%9}, {%0,%1,%2,%3};"
        : "+f"(c[0]), "+f"(c[1]), "+f"(c[2]), "+f"(c[3])
        : "r"(a[0]), "r"(a[1]), "r"(a[2]), "r"(a[3]), "r"(b[0]), "r"(b[1]));
}

#define CP_ASYNC16(dst, src) \
    asm volatile("cp.async.cg.shared.global [%0], [%1], 16;" \
                 :: "r"(dst), "l"(src) : "memory")
#define CP_ASYNC_COMMIT() \
    asm volatile("cp.async.commit_group;" ::: "memory")
#define CP_ASYNC_WAIT(n) \
    asm volatile("cp.async.wait_group %0;" :: "n"(n) : "memory")

// SW128-style swizzle on byte offsets within a 128B-row tile
__device__ __forceinline__ uint32_t swz(uint32_t off) {
    return off ^ ((off >> 3) & 0x70);
}

// exp(d / 0.07): 1 FMUL + 1 MUFU (hardware exp2), rel err ~1e-6
__device__ __forceinline__ float fast_exp_scaled(float d) {
    return __expf(d * INV_T);
}

// ============================================================================
// Kernel 1: L2-normalize rows -> bf16. One WARP per row: 6 float4 loads per
// lane, shuffle reduction (no smem, no __syncthreads), 6 uint2 bf16 stores.
// Also zeroes the accumulators and the output scalar.
// ============================================================================
__global__ __launch_bounds__(256) void normalize_kernel(
        const float4* __restrict__ feats4, float* __restrict__ out) {
    const int row  = blockIdx.x * 8 + (threadIdx.x >> 5);
    const int lane = threadIdx.x & 31;

    const float4* src = feats4 + (size_t)row * (DIM / 4);   // 192 float4/row
    float4 v[6];
    float ss = 0.f;
    #pragma unroll
    for (int i = 0; i < 6; ++i) {
        v[i] = src[lane + 32 * i];
        ss = fmaf(v[i].x, v[i].x, ss);
        ss = fmaf(v[i].y, v[i].y, ss);
        ss = fmaf(v[i].z, v[i].z, ss);
        ss = fmaf(v[i].w, v[i].w, ss);
    }
    #pragma unroll
    for (int o = 16; o; o >>= 1) ss += __shfl_xor_sync(0xFFFFFFFFu, ss, o);

    const float rn = 1.f / fmaxf(sqrtf(ss), 1e-12f);

    if (lane == 0) {
        g_rowsum[row] = 0.f;
        g_possum[row] = 0.f;
        if (row == 0) out[0] = 0.f;
    }

    uint2* dst = ((uint2*)g_fbf16) + (size_t)row * (DIM / 4);  // 8B = 4 bf16
    #pragma unroll
    for (int i = 0; i < 6; ++i) {
        __nv_bfloat162 lo = __floats2bfloat162_rn(v[i].x * rn, v[i].y * rn);
        __nv_bfloat162 hi = __floats2bfloat162_rn(v[i].z * rn, v[i].w * rn);
        uint2 pk;
        pk.x = *(uint32_t*)&lo;
        pk.y = *(uint32_t*)&hi;
        dst[lane + 32 * i] = pk;
    }
}

// ============================================================================
// Kernel 2: 128x128 bf16 GEMM tile (mma.sync) + fused exp / diag mask /
// row+col sums / positive-pair sums. Upper-triangular tiles only; the
// symmetric mirror is supplied via column sums.
// ============================================================================
__global__ __launch_bounds__(256, 2) void gemm_lse_kernel() {
    // 1D -> upper-triangular (bm, bn) mapping
    int idx = blockIdx.x, bm = 0, rem = GRID;
    while (idx >= rem) { idx -= rem; --rem; ++bm; }
    const int bn = bm + idx;

    extern __shared__ __align__(1024) char smem[];
    const uint32_t sb = smem_u32(smem);
    const int tid  = threadIdx.x;
    const int lane = tid & 31;
    const int w    = tid >> 5;            // 8 warps
    const int wm   = (w >> 2) * 64;       // warp row offset within tile
    const int wn   = (w & 3) * 32;        // warp col offset within tile
    const int m0 = bm * 128, n0 = bn * 128;
    const bool diag = (bm == bn);
    const bool adj  = (bn == bm + 1);     // may hold straddling positive pairs

    float* rowacc = (float*)(smem + SMEM_ACC);
    float* colacc = rowacc + 128;
    float* posacc = colacc + 128;
    if (tid < 128) { rowacc[tid] = 0.f; colacc[tid] = 0.f; posacc[tid] = 0.f; }

    const uint4* __restrict__ gA = g_fbf16 + (size_t)m0 * DIM_U4;
    const uint4* __restrict__ gB = g_fbf16 + (size_t)n0 * DIM_U4;

    float acc[4][4][4];
    #pragma unroll
    for (int i = 0; i < 4; ++i)
        #pragma unroll
        for (int j = 0; j < 4; ++j)
            #pragma unroll
            for (int k = 0; k < 4; ++k) acc[i][j][k] = 0.f;

    // ---- stage loader: 16B cp.async per thread x 4 iters per operand ----
    auto load_stage = [&](int c, int s) {
        uint32_t aBase = sb + s * STAGE_BYTES;
        uint32_t bBase = aBase + 16384;
        #pragma unroll
        for (int i = 0; i < 4; ++i) {
            int id = tid + i * 256;       // 1024 chunks: 128 rows x 8
            int r = id >> 3, ch = id & 7;
            uint32_t off = swz((uint32_t)(r * 128 + ch * 16));
            CP_ASYNC16(aBase + off, &gA[r * DIM_U4 + c * 8 + ch]);
            CP_ASYNC16(bBase + off, &gB[r * DIM_U4 + c * 8 + ch]);
        }
        CP_ASYNC_COMMIT();
    };

    // ---- compute one K=64 stage: 4 k16-steps x (4x4) mma per warp ----
    const int arow  = wm + (lane & 15);
    const uint32_t acolp = (uint32_t)((lane >> 4) << 4);
    const int brow  = wn + ((lane >> 4) << 3) + (lane & 7);
    const uint32_t bcolp = (uint32_t)(((lane >> 3) & 1) << 4);

    auto compute_stage = [&](int s) {
        uint32_t aBase = sb + s * STAGE_BYTES;
        uint32_t bBase = aBase + 16384;
        #pragma unroll
        for (int ks = 0; ks < 4; ++ks) {
            uint32_t af[4][4];
            #pragma unroll
            for (int mt = 0; mt < 4; ++mt) {
                uint32_t off = swz((uint32_t)((arow + mt * 16) * 128) +
                                   (uint32_t)(ks * 32) + acolp);
                ldsm_x4(af[mt], aBase + off);
            }
            uint32_t bf[4][2];
            #pragma unroll
            for (int p = 0; p < 2; ++p) {
                uint32_t t4[4];
                uint32_t off = swz((uint32_t)((brow + p * 16) * 128) +
                                   (uint32_t)(ks * 32) + bcolp);
                ldsm_x4(t4, bBase + off);
                bf[2 * p][0]     = t4[0]; bf[2 * p][1]     = t4[1];
                bf[2 * p + 1][0] = t4[2]; bf[2 * p + 1][1] = t4[3];
            }
            #pragma unroll
            for (int mt = 0; mt < 4; ++mt)
                #pragma unroll
                for (int nt = 0; nt < 4; ++nt)
                    mma16816(acc[mt][nt], af[mt], bf[nt]);
        }
    };

    // ---- 3-stage software pipeline, one sync per K-stage ----
    load_stage(0, 0);
    load_stage(1, 1);
    #pragma unroll 1
    for (int c = 0; c < NSTAGES; ++c) {
        if (c < NSTAGES - 1) { CP_ASYNC_WAIT(1); } else { CP_ASYNC_WAIT(0); }
        __syncthreads();                   // load(c) visible; compute(c-1) done
        if (c + 2 < NSTAGES) load_stage(c + 2, (c + 2) % 3);
        compute_stage(c % 3);
    }

    // ---- epilogue: exp + diag mask; row / col / positive partials ----
    float rowp[4][2], colp[4][2], posp[4][2];
    #pragma unroll
    for (int i = 0; i < 4; ++i) {
        rowp[i][0] = rowp[i][1] = 0.f;
        colp[i][0] = colp[i][1] = 0.f;
        posp[i][0] = posp[i][1] = 0.f;
    }
    const int rl0 = wm + (lane >> 2);
    const int cl0 = wn + 2 * (lane & 3);
    #pragma unroll
    for (int mt = 0; mt < 4; ++mt) {
        int r0 = rl0 + mt * 16, r1 = r0 + 8;
        #pragma unroll
        for (int nt = 0; nt < 4; ++nt) {
            int c0 = cl0 + nt * 8, c1 = c0 + 1;
            float e00 = fast_exp_scaled(acc[mt][nt][0]);
            float e01 = fast_exp_scaled(acc[mt][nt][1]);
            float e10 = fast_exp_scaled(acc[mt][nt][2]);
            float e11 = fast_exp_scaled(acc[mt][nt][3]);
            if (diag) {
                if (r0 == c0) e00 = 0.f;
                if (r0 == c1) e01 = 0.f;
                if (r1 == c0) e10 = 0.f;
                if (r1 == c1) e11 = 0.f;
                // positives: same global group of 3 (self already zeroed)
                int gr0 = (m0 + r0) / 3, gr1 = (m0 + r1) / 3;
                int gc0 = (n0 + c0) / 3, gc1 = (n0 + c1) / 3;
                posp[mt][0] += (gr0 == gc0 ? e00 : 0.f) + (gr0 == gc1 ? e01 : 0.f);
                posp[mt][1] += (gr1 == gc0 ? e10 : 0.f) + (gr1 == gc1 ? e11 : 0.f);
            }
            if (adj && mt == 3 && nt == 0) {
                // straddling group across the 128-boundary (128 % 3 != 0):
                // only rows n0-2..n0-1 x cols n0..n0+1 can qualify (<=2 elems)
                int gr1g = m0 + r1;
                if (gr1g >= n0 - 2 && c0 <= 1) {
                    if ((gr1g / 3) == ((n0 + c0) / 3)) {
                        atomicAdd(&g_possum[gr1g], e10);
                        atomicAdd(&g_possum[n0 + c0], e10);
                    }
                    if ((gr1g / 3) == ((n0 + c1) / 3)) {
                        atomicAdd(&g_possum[gr1g], e11);
                        atomicAdd(&g_possum[n0 + c1], e11);
                    }
                }
            }
            rowp[mt][0] += e00 + e01;
            rowp[mt][1] += e10 + e11;
            colp[nt][0] += e00 + e10;
            colp[nt][1] += e01 + e11;
        }
    }
    // row reduce: lanes sharing (lane>>2) hold the same rows
    #pragma unroll
    for (int mt = 0; mt < 4; ++mt)
        #pragma unroll
        for (int h = 0; h < 2; ++h) {
            float v = rowp[mt][h];
            v += __shfl_xor_sync(0xFFFFFFFFu, v, 1);
            v += __shfl_xor_sync(0xFFFFFFFFu, v, 2);
            float q = posp[mt][h];
            q += __shfl_xor_sync(0xFFFFFFFFu, q, 1);
            q += __shfl_xor_sync(0xFFFFFFFFu, q, 2);
            if ((lane & 3) == 0) {
                int rr = wm + mt * 16 + (lane >> 2) + 8 * h;
                atomicAdd(&rowacc[rr], v);
                if (diag) atomicAdd(&posacc[rr], q);
            }
        }
    // col reduce: lanes sharing (lane&3) hold the same cols
    #pragma unroll
    for (int nt = 0; nt < 4; ++nt)
        #pragma unroll
        for (int j = 0; j < 2; ++j) {
            float v = colp[nt][j];
            v += __shfl_xor_sync(0xFFFFFFFFu, v, 4);
            v += __shfl_xor_sync(0xFFFFFFFFu, v, 8);
            v += __shfl_xor_sync(0xFFFFFFFFu, v, 16);
            if (lane < 4)
                atomicAdd(&colacc[wn + nt * 8 + 2 * lane + j], v);
        }
    __syncthreads();
    if (tid < 128) {
        atomicAdd(&g_rowsum[m0 + tid], rowacc[tid]);
        if (!diag) atomicAdd(&g_rowsum[n0 + tid], colacc[tid]);
        if (diag)  atomicAdd(&g_possum[m0 + tid], posacc[tid]);
    }
}

// ============================================================================
// Kernel 3: parallel final reduction -> loss scalar (out zeroed in normalize)
// ============================================================================
__global__ void finalize_kernel(float* __restrict__ out) {
    int i = blockIdx.x * 256 + threadIdx.x;   // 24 x 256 = 6144 threads
    float v = logf(g_rowsum[i] / g_possum[i]);
    #pragma unroll
    for (int o = 16; o; o >>= 1) v += __shfl_xor_sync(0xFFFFFFFFu, v, o);
    __shared__ float sr[8];
    int lane = threadIdx.x & 31, wrp = threadIdx.x >> 5;
    if (lane == 0) sr[wrp] = v;
    __syncthreads();
    if (threadIdx.x < 8) {
        float s = sr[threadIdx.x];
        #pragma unroll
        for (int o = 4; o; o >>= 1) s += __shfl_xor_sync(0xFFu, s, o);
        if (threadIdx.x == 0) atomicAdd(out, s * (1.0f / (float)NROW));
    }
}

// ============================================================================
// Launch
// ============================================================================
extern "C" void kernel_launch(void* const* d_in, const int* in_sizes, int n_in,
                              void* d_out, int out_size) {
    const float4* feats4 = (const float4*)d_in[0];
    float* out = (float*)d_out;
    (void)in_sizes; (void)n_in; (void)out_size;

    normalize_kernel<<<NROW / 8, 256>>>(feats4, out);

    cudaFuncSetAttribute(gemm_lse_kernel,
                         cudaFuncAttributeMaxDynamicSharedMemorySize, SMEM_TOTAL);
    gemm_lse_kernel<<<NTILES, 256, SMEM_TOTAL>>>();

    finalize_kernel<<<NROW / 256, 256>>>(out);
}

// round 16
// speedup vs baseline: 1.1687x; 1.0015x over previous
#include <cuda_runtime.h>
#include <cuda_bf16.h>
#include <cstdint>

// ============================================================================
// Problem constants
// ============================================================================
static constexpr int NROW = 6144;
static constexpr int DIM  = 768;
static constexpr int DIM_U4 = DIM / 8;   // 96 uint4 per row (bf16)
static constexpr float INV_T = 14.285714285714286f;   // 1/0.07

// GEMM tiling: CTA 128x128, 8 warps (2x4), warp tile 64x32, K staged at 64
static constexpr int NSTAGES = DIM / 64;    // 12
static constexpr int GRID    = NROW / 128;  // 48
static constexpr int NTILES  = GRID * (GRID + 1) / 2;  // 1176 upper-tri tiles

// Dynamic SMEM: 3 stages x 32KB (A 16K + B 16K), then acc arrays
static constexpr int STAGE_BYTES = 32768;
static constexpr int SMEM_ACC    = 3 * STAGE_BYTES;     // 98304
static constexpr int SMEM_TOTAL  = SMEM_ACC + 1536;     // row/col/pos acc

// ============================================================================
// Device scratch (no runtime allocation allowed)
// ============================================================================
__device__ uint4 g_fbf16[NROW * DIM_U4];   // normalized feats, bf16 row-major
__device__ float g_rowsum[NROW];           // sum_{j!=i} exp(sim_ij)
__device__ float g_possum[NROW];           // sum over positives exp(sim_ij)

// ============================================================================
// PTX helpers (base ISA only — compiles for .target sm_103)
// ============================================================================
__device__ __forceinline__ uint32_t smem_u32(const void* p) {
    uint32_t a;
    asm("{ .reg .u64 t; cvta.to.shared.u64 t, %1; cvt.u32.u64 %0, t; }"
        : "=r"(a) : "l"(p));
    return a;
}

__device__ __forceinline__ void ldsm_x4(uint32_t r[4], uint32_t addr) {
    asm volatile("ldmatrix.sync.aligned.m8n8.x4.shared.b16 {%0,%1,%2,%3}, [%4];"
                 : "=r"(r[0]), "=r"(r[1]), "=r"(r[2]), "=r"(r[3]) : "r"(addr));
}

__device__ __forceinline__ void mma16816(float c[4], const uint32_t a[4],
                                         const uint32_t b[2]) {
    asm volatile(
        "mma.sync.aligned.m16n8k16.row.col.f32.bf16.bf16.f32 "
        "{%0,%1,%2,%3}, {%4,%5,%6,%7}, {%8,%9}, {%0,%1,%2,%3};"
        : "+f"(c[0]), "+f"(c[1]), "+f"(c[2]), "+f"(c[3])
        : "r"(a[0]), "r"(a[1]), "r"(a[2]), "r"(a[3]), "r"(b[0]), "r"(b[1]));
}

#define CP_ASYNC16(dst, src) \
    asm volatile("cp.async.cg.shared.global [%0], [%1], 16;" \
                 :: "r"(dst), "l"(src) : "memory")
#define CP_ASYNC_COMMIT() \
    asm volatile("cp.async.commit_group;" ::: "memory")
#define CP_ASYNC_WAIT(n) \
    asm volatile("cp.async.wait_group %0;" :: "n"(n) : "memory")

// SW128-style swizzle on byte offsets within a 128B-row tile
__device__ __forceinline__ uint32_t swz(uint32_t off) {
    return off ^ ((off >> 3) & 0x70);
}

// exp(d / 0.07): 1 FMUL + 1 MUFU (hardware exp2), rel err ~1e-6
__device__ __forceinline__ float fast_exp_scaled(float d) {
    return __expf(d * INV_T);
}

// ============================================================================
// Kernel 1: L2-normalize rows -> bf16. One WARP per row: 6 float4 loads per
// lane, shuffle reduction (no smem, no __syncthreads), 6 uint2 bf16 stores.
// Also zeroes the accumulators and the output scalar.
// ============================================================================
__global__ __launch_bounds__(256) void normalize_kernel(
        const float4* __restrict__ feats4, float* __restrict__ out) {
    const int row  = blockIdx.x * 8 + (threadIdx.x >> 5);
    const int lane = threadIdx.x & 31;

    const float4* src = feats4 + (size_t)row * (DIM / 4);   // 192 float4/row
    float4 v[6];
    float ss = 0.f;
    #pragma unroll
    for (int i = 0; i < 6; ++i) {
        v[i] = src[lane + 32 * i];
        ss = fmaf(v[i].x, v[i].x, ss);
        ss = fmaf(v[i].y, v[i].y, ss);
        ss = fmaf(v[i].z, v[i].z, ss);
        ss = fmaf(v[i].w, v[i].w, ss);
    }
    #pragma unroll
    for (int o = 16; o; o >>= 1) ss += __shfl_xor_sync(0xFFFFFFFFu, ss, o);

    const float rn = 1.f / fmaxf(sqrtf(ss), 1e-12f);

    if (lane == 0) {
        g_rowsum[row] = 0.f;
        g_possum[row] = 0.f;
        if (row == 0) out[0] = 0.f;
    }

    uint2* dst = ((uint2*)g_fbf16) + (size_t)row * (DIM / 4);  // 8B = 4 bf16
    #pragma unroll
    for (int i = 0; i < 6; ++i) {
        __nv_bfloat162 lo = __floats2bfloat162_rn(v[i].x * rn, v[i].y * rn);
        __nv_bfloat162 hi = __floats2bfloat162_rn(v[i].z * rn, v[i].w * rn);
        uint2 pk;
        pk.x = *(uint32_t*)&lo;
        pk.y = *(uint32_t*)&hi;
        dst[lane + 32 * i] = pk;
    }
}

// ============================================================================
// Kernel 2: 128x128 bf16 GEMM tile (mma.sync) + fused exp / diag mask /
// row+col sums / positive-pair sums. Upper-triangular tiles only; the
// symmetric mirror is supplied via column sums.
// ============================================================================
__global__ __launch_bounds__(256, 2) void gemm_lse_kernel() {
    // 1D -> upper-triangular (bm, bn) mapping
    int idx = blockIdx.x, bm = 0, rem = GRID;
    while (idx >= rem) { idx -= rem; --rem; ++bm; }
    const int bn = bm + idx;

    extern __shared__ __align__(1024) char smem[];
    const uint32_t sb = smem_u32(smem);
    const int tid  = threadIdx.x;
    const int lane = tid & 31;
    const int w    = tid >> 5;            // 8 warps
    const int wm   = (w >> 2) * 64;       // warp row offset within tile
    const int wn   = (w & 3) * 32;        // warp col offset within tile
    const int m0 = bm * 128, n0 = bn * 128;
    const bool diag = (bm == bn);
    const bool adj  = (bn == bm + 1);     // may hold straddling positive pairs

    float* rowacc = (float*)(smem + SMEM_ACC);
    float* colacc = rowacc + 128;
    float* posacc = colacc + 128;
    if (tid < 128) { rowacc[tid] = 0.f; colacc[tid] = 0.f; posacc[tid] = 0.f; }

    const uint4* __restrict__ gA = g_fbf16 + (size_t)m0 * DIM_U4;
    const uint4* __restrict__ gB = g_fbf16 + (size_t)n0 * DIM_U4;

    float acc[4][4][4];
    #pragma unroll
    for (int i = 0; i < 4; ++i)
        #pragma unroll
        for (int j = 0; j < 4; ++j)
            #pragma unroll
            for (int k = 0; k < 4; ++k) acc[i][j][k] = 0.f;

    // ---- stage loader: 16B cp.async per thread x 4 iters per operand ----
    auto load_stage = [&](int c, int s) {
        uint32_t aBase = sb + s * STAGE_BYTES;
        uint32_t bBase = aBase + 16384;
        #pragma unroll
        for (int i = 0; i < 4; ++i) {
            int id = tid + i * 256;       // 1024 chunks: 128 rows x 8
            int r = id >> 3, ch = id & 7;
            uint32_t off = swz((uint32_t)(r * 128 + ch * 16));
            CP_ASYNC16(aBase + off, &gA[r * DIM_U4 + c * 8 + ch]);
            CP_ASYNC16(bBase + off, &gB[r * DIM_U4 + c * 8 + ch]);
        }
        CP_ASYNC_COMMIT();
    };

    // ---- compute one K=64 stage: 4 k16-steps x (4x4) mma per warp ----
    const int arow  = wm + (lane & 15);
    const uint32_t acolp = (uint32_t)((lane >> 4) << 4);
    const int brow  = wn + ((lane >> 4) << 3) + (lane & 7);
    const uint32_t bcolp = (uint32_t)(((lane >> 3) & 1) << 4);

    auto compute_stage = [&](int s) {
        uint32_t aBase = sb + s * STAGE_BYTES;
        uint32_t bBase = aBase + 16384;
        #pragma unroll
        for (int ks = 0; ks < 4; ++ks) {
            uint32_t af[4][4];
            #pragma unroll
            for (int mt = 0; mt < 4; ++mt) {
                uint32_t off = swz((uint32_t)((arow + mt * 16) * 128) +
                                   (uint32_t)(ks * 32) + acolp);
                ldsm_x4(af[mt], aBase + off);
            }
            uint32_t bf[4][2];
            #pragma unroll
            for (int p = 0; p < 2; ++p) {
                uint32_t t4[4];
                uint32_t off = swz((uint32_t)((brow + p * 16) * 128) +
                                   (uint32_t)(ks * 32) + bcolp);
                ldsm_x4(t4, bBase + off);
                bf[2 * p][0]     = t4[0]; bf[2 * p][1]     = t4[1];
                bf[2 * p + 1][0] = t4[2]; bf[2 * p + 1][1] = t4[3];
            }
            #pragma unroll
            for (int mt = 0; mt < 4; ++mt)
                #pragma unroll
                for (int nt = 0; nt < 4; ++nt)
                    mma16816(acc[mt][nt], af[mt], bf[nt]);
        }
    };

    // ---- 3-stage software pipeline, one sync per K-stage ----
    load_stage(0, 0);
    load_stage(1, 1);
    #pragma unroll 1
    for (int c = 0; c < NSTAGES; ++c) {
        if (c < NSTAGES - 1) { CP_ASYNC_WAIT(1); } else { CP_ASYNC_WAIT(0); }
        __syncthreads();                   // load(c) visible; compute(c-1) done
        if (c + 2 < NSTAGES) load_stage(c + 2, (c + 2) % 3);
        compute_stage(c % 3);
    }

    // ---- epilogue: exp + diag mask; row / col / positive partials ----
    float rowp[4][2], colp[4][2], posp[4][2];
    #pragma unroll
    for (int i = 0; i < 4; ++i) {
        rowp[i][0] = rowp[i][1] = 0.f;
        colp[i][0] = colp[i][1] = 0.f;
        posp[i][0] = posp[i][1] = 0.f;
    }
    const int rl0 = wm + (lane >> 2);
    const int cl0 = wn + 2 * (lane & 3);
    #pragma unroll
    for (int mt = 0; mt < 4; ++mt) {
        int r0 = rl0 + mt * 16, r1 = r0 + 8;
        #pragma unroll
        for (int nt = 0; nt < 4; ++nt) {
            int c0 = cl0 + nt * 8, c1 = c0 + 1;
            float e00 = fast_exp_scaled(acc[mt][nt][0]);
            float e01 = fast_exp_scaled(acc[mt][nt][1]);
            float e10 = fast_exp_scaled(acc[mt][nt][2]);
            float e11 = fast_exp_scaled(acc[mt][nt][3]);
            if (diag) {
                if (r0 == c0) e00 = 0.f;
                if (r0 == c1) e01 = 0.f;
                if (r1 == c0) e10 = 0.f;
                if (r1 == c1) e11 = 0.f;
                // positives: same global group of 3 (self already zeroed)
                int gr0 = (m0 + r0) / 3, gr1 = (m0 + r1) / 3;
                int gc0 = (n0 + c0) / 3, gc1 = (n0 + c1) / 3;
                posp[mt][0] += (gr0 == gc0 ? e00 : 0.f) + (gr0 == gc1 ? e01 : 0.f);
                posp[mt][1] += (gr1 == gc0 ? e10 : 0.f) + (gr1 == gc1 ? e11 : 0.f);
            }
            if (adj && mt == 3 && nt == 0) {
                // straddling group across the 128-boundary (128 % 3 != 0):
                // only rows n0-2..n0-1 x cols n0..n0+1 can qualify (<=2 elems)
                int gr1g = m0 + r1;
                if (gr1g >= n0 - 2 && c0 <= 1) {
                    if ((gr1g / 3) == ((n0 + c0) / 3)) {
                        atomicAdd(&g_possum[gr1g], e10);
                        atomicAdd(&g_possum[n0 + c0], e10);
                    }
                    if ((gr1g / 3) == ((n0 + c1) / 3)) {
                        atomicAdd(&g_possum[gr1g], e11);
                        atomicAdd(&g_possum[n0 + c1], e11);
                    }
                }
            }
            rowp[mt][0] += e00 + e01;
            rowp[mt][1] += e10 + e11;
            colp[nt][0] += e00 + e10;
            colp[nt][1] += e01 + e11;
        }
    }
    // row reduce: lanes sharing (lane>>2) hold the same rows
    #pragma unroll
    for (int mt = 0; mt < 4; ++mt)
        #pragma unroll
        for (int h = 0; h < 2; ++h) {
            float v = rowp[mt][h];
            v += __shfl_xor_sync(0xFFFFFFFFu, v, 1);
            v += __shfl_xor_sync(0xFFFFFFFFu, v, 2);
            float q = posp[mt][h];
            q += __shfl_xor_sync(0xFFFFFFFFu, q, 1);
            q += __shfl_xor_sync(0xFFFFFFFFu, q, 2);
            if ((lane & 3) == 0) {
                int rr = wm + mt * 16 + (lane >> 2) + 8 * h;
                atomicAdd(&rowacc[rr], v);
                if (diag) atomicAdd(&posacc[rr], q);
            }
        }
    // col reduce: lanes sharing (lane&3) hold the same cols
    #pragma unroll
    for (int nt = 0; nt < 4; ++nt)
        #pragma unroll
        for (int j = 0; j < 2; ++j) {
            float v = colp[nt][j];
            v += __shfl_xor_sync(0xFFFFFFFFu, v, 4);
            v += __shfl_xor_sync(0xFFFFFFFFu, v, 8);
            v += __shfl_xor_sync(0xFFFFFFFFu, v, 16);
            if (lane < 4)
                atomicAdd(&colacc[wn + nt * 8 + 2 * lane + j], v);
        }
    __syncthreads();
    if (tid < 128) {
        atomicAdd(&g_rowsum[m0 + tid], rowacc[tid]);
        if (!diag) atomicAdd(&g_rowsum[n0 + tid], colacc[tid]);
        if (diag)  atomicAdd(&g_possum[m0 + tid], posacc[tid]);
    }
}

// ============================================================================
// Kernel 3: parallel final reduction -> loss scalar (out zeroed in normalize)
// ============================================================================
__global__ void finalize_kernel(float* __restrict__ out) {
    int i = blockIdx.x * 256 + threadIdx.x;   // 24 x 256 = 6144 threads
    float v = logf(g_rowsum[i] / g_possum[i]);
    #pragma unroll
    for (int o = 16; o; o >>= 1) v += __shfl_xor_sync(0xFFFFFFFFu, v, o);
    __shared__ float sr[8];
    int lane = threadIdx.x & 31, wrp = threadIdx.x >> 5;
    if (lane == 0) sr[wrp] = v;
    __syncthreads();
    if (threadIdx.x < 8) {
        float s = sr[threadIdx.x];
        #pragma unroll
        for (int o = 4; o; o >>= 1) s += __shfl_xor_sync(0xFFu, s, o);
        if (threadIdx.x == 0) atomicAdd(out, s * (1.0f / (float)NROW));
    }
}

// ============================================================================
// Launch
// ============================================================================
extern "C" void kernel_launch(void* const* d_in, const int* in_sizes, int n_in,
                              void* d_out, int out_size) {
    const float4* feats4 = (const float4*)d_in[0];
    float* out = (float*)d_out;
    (void)in_sizes; (void)n_in; (void)out_size;

    normalize_kernel<<<NROW / 8, 256>>>(feats4, out);

    cudaFuncSetAttribute(gemm_lse_kernel,
                         cudaFuncAttributeMaxDynamicSharedMemorySize, SMEM_TOTAL);
    gemm_lse_kernel<<<NTILES, 256, SMEM_TOTAL>>>();

    finalize_kernel<<<NROW / 256, 256>>>(out);
}